// round 3
// baseline (speedup 1.0000x reference)
#include <cuda_runtime.h>
#include <cstdint>

#define N_PTS 262144
#define K_CEN 512
#define D_DIM 128
#define LDA   132   // padded row stride in floats (bank-conflict-free)
#define MARGIN 0.25f

// scratch (device globals: allocation-free per harness rules)
__device__ float g_xsq[N_PTS];
__device__ float g_csq[K_CEN];
__device__ int   g_nflag;
__device__ int   g_flag[N_PTS];

static __device__ __forceinline__ uint32_t f2tf32(float f) {
    uint32_t r;
    asm("cvt.rna.tf32.f32 %0, %1;" : "=r"(r) : "f"(f));
    return r;
}

static __device__ __forceinline__ void mma_tf32(float c[4], const uint32_t a[4],
                                                const uint32_t b[2]) {
    asm volatile(
        "mma.sync.aligned.m16n8k8.row.col.f32.tf32.tf32.f32 "
        "{%0,%1,%2,%3}, {%4,%5,%6,%7}, {%8,%9}, {%0,%1,%2,%3};"
        : "+f"(c[0]), "+f"(c[1]), "+f"(c[2]), "+f"(c[3])
        : "r"(a[0]), "r"(a[1]), "r"(a[2]), "r"(a[3]), "r"(b[0]), "r"(b[1]));
}

// ---------------- prologue: squared norms (one warp per row) ----------------
__global__ void sq_kernel(const float* __restrict__ x, int nrows, int which) {
    if (which && blockIdx.x == 0 && threadIdx.x == 0) g_nflag = 0;
    int w = (blockIdx.x * blockDim.x + threadIdx.x) >> 5;
    int l = threadIdx.x & 31;
    if (w >= nrows) return;
    float4 v = *(const float4*)(x + (size_t)w * D_DIM + l * 4);
    float s = v.x * v.x + v.y * v.y + v.z * v.z + v.w * v.w;
    #pragma unroll
    for (int o = 16; o; o >>= 1) s += __shfl_xor_sync(0xffffffffu, s, o);
    if (l == 0) {
        if (which) g_csq[w] = s;
        else       g_xsq[w] = s;
    }
}

// ---------------- main kernel ----------------
// CTA = 128 points x all 512 centroids (4 chunks of 128).
// 8 warps: wm = wid%4 (M offset 32*wm), wn = wid/4 (N offset 64*wn).
// Warp tile: 32 (centroids) x 64 (points) via m16n8k8 tf32 mma.
#define SMEM_BYTES (2 * 128 * LDA * 4 + K_CEN * 4 + 128 * 4 + 128 * 4 * 8 + 128 * 4 * 4)

__global__ void __launch_bounds__(256, 1)
kmeans_main(const float* __restrict__ inp, const float* __restrict__ cen,
            float* __restrict__ dist_out, float* __restrict__ assign_out)
{
    extern __shared__ char smem[];
    uint32_t* sA   = (uint32_t*)smem;             // centroid chunk 128 x LDA (tf32)
    uint32_t* sX   = sA + 128 * LDA;              // points tile   128 x LDA (tf32)
    float* s_csq   = (float*)(sX + 128 * LDA);    // 512
    float* s_xsq   = s_csq + K_CEN;               // 128
    unsigned long long* s_e = (unsigned long long*)(s_xsq + 128);  // [128][4]
    float* s_d2    = (float*)(s_e + 128 * 4);     // [128][4]

    const int tid = threadIdx.x, wid = tid >> 5, l = tid & 31;
    const int wm = wid & 3, wn = wid >> 2;
    const int gid = l >> 2, tig = l & 3;          // mma groupID / thread-in-group
    const int n0 = blockIdx.x * 128;

    // --- loads: points tile (tf32), norms ---
    {
        const float* xs = inp + (size_t)n0 * D_DIM;
        #pragma unroll
        for (int i = 0; i < 16; i++) {
            int idx = tid + i * 256;
            int r = idx >> 5, c = (idx & 31) * 4;
            float4 v = *(const float4*)(xs + r * D_DIM + c);
            uint4 t = { f2tf32(v.x), f2tf32(v.y), f2tf32(v.z), f2tf32(v.w) };
            *(uint4*)(sX + r * LDA + c) = t;
        }
        for (int i = tid; i < K_CEN; i += 256) s_csq[i] = g_csq[i];
        if (tid < 128) s_xsq[tid] = g_xsq[n0 + tid];
    }

    // running per-lane best/second: 16 slots = 8 n-tiles x 2 owned cols
    float bd[16], b2[16];
    int   bk[16];
    #pragma unroll
    for (int s = 0; s < 16; s++) { bd[s] = 3.4e38f; b2[s] = 3.4e38f; bk[s] = 0; }

    for (int ch = 0; ch < 4; ch++) {
        __syncthreads();   // prev-chunk mma reads of sA done
        {
            const float* cs = cen + (size_t)(ch * 128) * D_DIM;
            #pragma unroll
            for (int i = 0; i < 16; i++) {
                int idx = tid + i * 256;
                int r = idx >> 5, c = (idx & 31) * 4;
                float4 v = *(const float4*)(cs + r * D_DIM + c);
                uint4 t = { f2tf32(v.x), f2tf32(v.y), f2tf32(v.z), f2tf32(v.w) };
                *(uint4*)(sA + r * LDA + c) = t;
            }
        }
        __syncthreads();

        float acc[2][8][4];
        #pragma unroll
        for (int mt = 0; mt < 2; mt++)
            #pragma unroll
            for (int nt = 0; nt < 8; nt++)
                #pragma unroll
                for (int j = 0; j < 4; j++) acc[mt][nt][j] = 0.0f;

        #pragma unroll
        for (int kd = 0; kd < 16; kd++) {
            const int d0 = kd * 8;
            uint32_t a[2][4];
            #pragma unroll
            for (int mt = 0; mt < 2; mt++) {
                int r0 = wm * 32 + mt * 16 + gid;
                a[mt][0] = sA[r0 * LDA + d0 + tig];
                a[mt][1] = sA[(r0 + 8) * LDA + d0 + tig];
                a[mt][2] = sA[r0 * LDA + d0 + 4 + tig];
                a[mt][3] = sA[(r0 + 8) * LDA + d0 + 4 + tig];
            }
            uint32_t b[8][2];
            #pragma unroll
            for (int nt = 0; nt < 8; nt++) {
                int n = wn * 64 + nt * 8 + gid;
                b[nt][0] = sX[n * LDA + d0 + tig];
                b[nt][1] = sX[n * LDA + d0 + 4 + tig];
            }
            #pragma unroll
            for (int mt = 0; mt < 2; mt++)
                #pragma unroll
                for (int nt = 0; nt < 8; nt++)
                    mma_tf32(acc[mt][nt], a[mt], b[nt]);
        }

        // --- epilogue: distances out + running best/second ---
        #pragma unroll
        for (int mt = 0; mt < 2; mt++) {
            const int k0 = ch * 128 + wm * 32 + mt * 16 + gid;
            const float cs0 = s_csq[k0], cs8 = s_csq[k0 + 8];
            #pragma unroll
            for (int nt = 0; nt < 8; nt++) {
                const int nl = wn * 64 + nt * 8 + tig * 2;
                const float xs0 = s_xsq[nl], xs1 = s_xsq[nl + 1];
                float d00 = fmaf(-2.0f, acc[mt][nt][0], cs0 + xs0);
                float d01 = fmaf(-2.0f, acc[mt][nt][1], cs0 + xs1);
                float d10 = fmaf(-2.0f, acc[mt][nt][2], cs8 + xs0);
                float d11 = fmaf(-2.0f, acc[mt][nt][3], cs8 + xs1);
                const size_t ng = (size_t)n0 + nl;
                float2 v0 = { d00, d01 }, v1 = { d10, d11 };
                *(float2*)(dist_out + (size_t)k0 * N_PTS + ng) = v0;
                *(float2*)(dist_out + (size_t)(k0 + 8) * N_PTS + ng) = v1;
                const int s0 = nt * 2, s1 = nt * 2 + 1;
                if (d00 < bd[s0]) { b2[s0] = bd[s0]; bd[s0] = d00; bk[s0] = k0; }
                else if (d00 < b2[s0]) b2[s0] = d00;
                if (d10 < bd[s0]) { b2[s0] = bd[s0]; bd[s0] = d10; bk[s0] = k0 + 8; }
                else if (d10 < b2[s0]) b2[s0] = d10;
                if (d01 < bd[s1]) { b2[s1] = bd[s1]; bd[s1] = d01; bk[s1] = k0; }
                else if (d01 < b2[s1]) b2[s1] = d01;
                if (d11 < bd[s1]) { b2[s1] = bd[s1]; bd[s1] = d11; bk[s1] = k0 + 8; }
                else if (d11 < b2[s1]) b2[s1] = d11;
            }
        }
    }

    // --- reduce (best, second) over lanes sharing a column, then to smem ---
    #pragma unroll
    for (int s = 0; s < 16; s++) {
        unsigned long long e =
            (((unsigned long long)__float_as_uint(bd[s])) << 32) | (unsigned)bk[s];
        float d2 = b2[s];
        #pragma unroll
        for (int off = 4; off <= 16; off <<= 1) {
            unsigned long long oe = __shfl_xor_sync(0xffffffffu, e, off);
            float od2 = __shfl_xor_sync(0xffffffffu, d2, off);
            float od1 = __uint_as_float((unsigned)(oe >> 32));
            float md1 = __uint_as_float((unsigned)(e >> 32));
            if (oe < e) { d2 = fminf(od2, md1); e = oe; }
            else        { d2 = fminf(d2, od1); }
        }
        if (l < 4) {
            int col = wn * 64 + (s >> 1) * 8 + l * 2 + (s & 1);
            s_e[col * 4 + wm] = e;
            s_d2[col * 4 + wm] = d2;
        }
    }
    __syncthreads();
    if (tid < 128) {
        unsigned long long be = s_e[tid * 4];
        #pragma unroll
        for (int j = 1; j < 4; j++) { unsigned long long v = s_e[tid * 4 + j]; if (v < be) be = v; }
        float d1 = __uint_as_float((unsigned)(be >> 32));
        float d2 = 3.4e38f;
        #pragma unroll
        for (int j = 0; j < 4; j++) {
            unsigned long long v = s_e[tid * 4 + j];
            float vd = __uint_as_float((unsigned)(v >> 32));
            d2 = fminf(d2, (v == be) ? s_d2[tid * 4 + j] : vd);
        }
        int n = n0 + tid;
        assign_out[n] = (float)(unsigned)(be & 0xFFFFFFFFull);
        if (d2 - d1 < MARGIN) {
            int slot = atomicAdd(&g_nflag, 1);
            g_flag[slot] = n;
        }
    }
}

// ---------------- exact fp64 refinement for near-tied points ----------------
__global__ void __launch_bounds__(256, 2)
refine_kernel(const float* __restrict__ inp, const float* __restrict__ cen,
              float* __restrict__ assign_out)
{
    __shared__ float sx[8][D_DIM];
    const int wid = threadIdx.x >> 5, l = threadIdx.x & 31;
    const int gw = blockIdx.x * 8 + wid;
    const int nW = gridDim.x * 8;
    const int nf = g_nflag;
    for (int it = gw; it < nf; it += nW) {
        const int n = g_flag[it];
        for (int d = l; d < D_DIM; d += 32)
            sx[wid][d] = inp[(size_t)n * D_DIM + d];
        __syncwarp();
        double bestd = 1e300;
        int bestk = 0;
        for (int j = 0; j < 16; j++) {
            const int k = j * 32 + l;
            const float* c = cen + (size_t)k * D_DIM;
            double acc = 0.0;
            #pragma unroll 8
            for (int d = 0; d < D_DIM; d++) {
                double diff = (double)sx[wid][d] - (double)c[d];
                acc = fma(diff, diff, acc);
            }
            if (acc < bestd) { bestd = acc; bestk = k; }
        }
        #pragma unroll
        for (int off = 16; off; off >>= 1) {
            double od = __shfl_xor_sync(0xffffffffu, bestd, off);
            int ok = __shfl_xor_sync(0xffffffffu, bestk, off);
            if (od < bestd || (od == bestd && ok < bestk)) { bestd = od; bestk = ok; }
        }
        if (l == 0) assign_out[n] = (float)bestk;
        __syncwarp();
    }
}

// ---------------- launch ----------------
extern "C" void kernel_launch(void* const* d_in, const int* in_sizes, int n_in,
                              void* d_out, int out_size) {
    const float* inp = (const float*)d_in[0];
    const float* cen = (const float*)d_in[1];
    float* dist = (float*)d_out;
    long long need = (long long)K_CEN * N_PTS + N_PTS;
    float* assign = ((long long)out_size >= need) ? dist + (size_t)K_CEN * N_PTS
                                                  : dist;  // fallback, unused

    cudaFuncSetAttribute(kmeans_main, cudaFuncAttributeMaxDynamicSharedMemorySize,
                         SMEM_BYTES);

    sq_kernel<<<N_PTS / 8, 256>>>(inp, N_PTS, 0);   // ||x||^2
    sq_kernel<<<K_CEN / 8, 256>>>(cen, K_CEN, 1);   // ||c||^2 + zero flag counter
    kmeans_main<<<N_PTS / 128, 256, SMEM_BYTES>>>(inp, cen, dist, assign);
    refine_kernel<<<296, 256>>>(inp, cen, assign);
}

// round 4
// speedup vs baseline: 3.9235x; 3.9235x over previous
#include <cuda_runtime.h>
#include <cstdint>

typedef unsigned long long ull;

#define N_PTS 262144
#define K_CEN 512
#define D_DIM 128
#define MARGIN 0.02f

// scratch (device globals: allocation-free per harness rules)
__device__ float g_xsq[N_PTS];
__device__ float g_csq[K_CEN];
__device__ float g_ct[D_DIM * K_CEN];   // centroids transposed [d][k]
__device__ int   g_nflag;
__device__ int   g_flag[N_PTS];

// ---------------- packed f32x2 helpers (Blackwell FFMA2) ----------------
#define FMA2(d_, a_, b_) \
    asm("fma.rn.f32x2 %0, %1, %2, %0;" : "+l"(d_) : "l"(a_), "l"(b_))
#define ADD2(d_, a_, b_) \
    asm("add.rn.f32x2 %0, %1, %2;" : "=l"(d_) : "l"(a_), "l"(b_))
static __device__ __forceinline__ ull pack2(float lo, float hi) {
    ull r; asm("mov.b64 %0, {%1, %2};" : "=l"(r) : "f"(lo), "f"(hi)); return r;
}
static __device__ __forceinline__ float2 unpack2(ull v) {
    float2 r; asm("mov.b64 {%0, %1}, %2;" : "=f"(r.x), "=f"(r.y) : "l"(v)); return r;
}

// ---------------- prologue: squared norms (one warp per row) ----------------
__global__ void sq_kernel(const float* __restrict__ x, int nrows, int which) {
    if (which && blockIdx.x == 0 && threadIdx.x == 0) g_nflag = 0;
    int w = (blockIdx.x * blockDim.x + threadIdx.x) >> 5;
    int l = threadIdx.x & 31;
    if (w >= nrows) return;
    float4 v = *(const float4*)(x + (size_t)w * D_DIM + l * 4);
    float s = v.x * v.x + v.y * v.y + v.z * v.z + v.w * v.w;
    #pragma unroll
    for (int o = 16; o; o >>= 1) s += __shfl_xor_sync(0xffffffffu, s, o);
    if (l == 0) {
        if (which) g_csq[w] = s;
        else       g_xsq[w] = s;
    }
}

// ---------------- centroid transpose: [512][128] -> g_ct [128][512] ----------
__global__ void transpose_c(const float* __restrict__ src) {
    __shared__ float t[32][33];
    int n0 = blockIdx.x * 32, d0 = blockIdx.y * 32;
    int tx = threadIdx.x & 31, ty = threadIdx.x >> 5;   // 256 thr: ty 0..7
    #pragma unroll
    for (int i = 0; i < 4; i++)
        t[ty + i * 8][tx] = src[(size_t)(n0 + ty + i * 8) * D_DIM + d0 + tx];
    __syncthreads();
    #pragma unroll
    for (int i = 0; i < 4; i++)
        g_ct[(size_t)(d0 + ty + i * 8) * K_CEN + n0 + tx] = t[tx][ty + i * 8];
}

// ---------------- main kernel ----------------
// CTA = 128 points (n) x 512 centroids (8 passes of 64 m).
// 8 warps: wm = wid>>2 (m half), wn = wid&3 (n quarter).
// Thread tile: 8 m x 4 n, acc = f32x2[4 m-pairs][4 n].
// smem: sX [128 d][128 n], sA [128 d][64 m], + norms + argmin combine.
#define SMEM_FLOATS (128 * 128 + 128 * 64 + K_CEN + 128)
#define SMEM_BYTES  (SMEM_FLOATS * 4 + 128 * 8 * 2)

__global__ void __launch_bounds__(256, 2)
kmeans_main(const float* __restrict__ inp,
            float* __restrict__ dist_out, float* __restrict__ assign_out)
{
    extern __shared__ float sm[];
    float* sX    = sm;                 // [d][n] 128x128
    float* sA    = sX + 128 * 128;     // [d][m] 128x64
    float* s_csq = sA + 128 * 64;      // 512
    float* s_xsq = s_csq + K_CEN;      // 128
    ull*   s_e   = (ull*)(s_xsq + 128);// 128
    ull*   s_e2  = s_e + 128;          // 128

    const int tid = threadIdx.x;
    const int l = tid & 31, wid = tid >> 5;
    const int wm = wid >> 2, wn = wid & 3;
    const int lm = l >> 3, ln = l & 7;
    const int n0 = blockIdx.x * 128;
    const int nl = wn * 32 + ln * 4;       // this thread's local col base

    // ---- load + transpose X tile into sX[d][n] (staging in sA space) ----
    {
        float (*stg)[33] = (float (*)[33])sA;   // 32x33 staging, reused 16x
        const int rr = tid >> 3, c4 = (tid & 7) * 4;   // read mapping
        const int tx = tid & 31, rg = tid >> 5;        // write mapping
        for (int st = 0; st < 16; st++) {
            int sn = st & 3, sd = st >> 2;             // subtile (n, d)
            float4 v = *(const float4*)(inp +
                (size_t)(n0 + sn * 32 + rr) * D_DIM + sd * 32 + c4);
            stg[rr][c4 + 0] = v.x; stg[rr][c4 + 1] = v.y;
            stg[rr][c4 + 2] = v.z; stg[rr][c4 + 3] = v.w;
            __syncthreads();
            #pragma unroll
            for (int j = 0; j < 4; j++)
                sX[(sd * 32 + rg * 4 + j) * 128 + sn * 32 + tx] = stg[tx][rg * 4 + j];
            __syncthreads();
        }
        for (int i = tid; i < K_CEN; i += 256) s_csq[i] = g_csq[i];
        if (tid < 128) {
            s_xsq[tid] = g_xsq[n0 + tid];
            s_e[tid] = ~0ull; s_e2[tid] = ~0ull;
        }
    }
    __syncthreads();

    ull xs2[4];
    #pragma unroll
    for (int j = 0; j < 4; j++) { float v = s_xsq[nl + j]; xs2[j] = pack2(v, v); }
    const ull neg2 = pack2(-2.0f, -2.0f);

    float bd[4], bs[4];
    int   bk[4];
    #pragma unroll
    for (int j = 0; j < 4; j++) { bd[j] = 3.4e38f; bs[j] = 3.4e38f; bk[j] = 0; }

    const float* pa0 = sA + wm * 32 + lm * 8;
    const float* pb0 = sX + nl;

    for (int pass = 0; pass < 8; pass++) {
        // load sA [128 d][64 m] from g_ct (L2-resident)
        {
            const int k0p = pass * 64;
            #pragma unroll
            for (int i = 0; i < 8; i++) {
                int idx = tid + i * 256;
                int d = idx >> 4, mq = (idx & 15) * 4;
                *(float4*)(sA + d * 64 + mq) =
                    *(const float4*)(g_ct + (size_t)d * K_CEN + k0p + mq);
            }
        }
        __syncthreads();

        ull acc[4][4];
        #pragma unroll
        for (int mp = 0; mp < 4; mp++)
            #pragma unroll
            for (int j = 0; j < 4; j++) acc[mp][j] = 0ull;

        #pragma unroll 4
        for (int d = 0; d < D_DIM; d++) {
            ulonglong2 A0 = *(const ulonglong2*)(pa0 + d * 64);
            ulonglong2 A1 = *(const ulonglong2*)(pa0 + d * 64 + 4);
            float4 bv = *(const float4*)(pb0 + d * 128);
            ull b0 = pack2(bv.x, bv.x), b1 = pack2(bv.y, bv.y);
            ull b2 = pack2(bv.z, bv.z), b3 = pack2(bv.w, bv.w);
            FMA2(acc[0][0], A0.x, b0); FMA2(acc[0][1], A0.x, b1);
            FMA2(acc[0][2], A0.x, b2); FMA2(acc[0][3], A0.x, b3);
            FMA2(acc[1][0], A0.y, b0); FMA2(acc[1][1], A0.y, b1);
            FMA2(acc[1][2], A0.y, b2); FMA2(acc[1][3], A0.y, b3);
            FMA2(acc[2][0], A1.x, b0); FMA2(acc[2][1], A1.x, b1);
            FMA2(acc[2][2], A1.x, b2); FMA2(acc[2][3], A1.x, b3);
            FMA2(acc[3][0], A1.y, b0); FMA2(acc[3][1], A1.y, b1);
            FMA2(acc[3][2], A1.y, b2); FMA2(acc[3][3], A1.y, b3);
        }
        __syncthreads();   // all warps done reading sA before next pass load

        // ---- epilogue: distances out + running best/second ----
        const int kb = pass * 64 + wm * 32 + lm * 8;
        #pragma unroll
        for (int mp = 0; mp < 4; mp++) {
            float2 cs = *(const float2*)(s_csq + kb + mp * 2);
            ull cs2 = pack2(cs.x, cs.y);
            float2 dv[4];
            #pragma unroll
            for (int j = 0; j < 4; j++) {
                ull t; ADD2(t, cs2, xs2[j]);
                FMA2(t, acc[mp][j], neg2);     // t = -2*dot + (c^2 + x^2)
                dv[j] = unpack2(t);
            }
            const int k0 = kb + mp * 2;
            float4 v0 = make_float4(dv[0].x, dv[1].x, dv[2].x, dv[3].x);
            float4 v1 = make_float4(dv[0].y, dv[1].y, dv[2].y, dv[3].y);
            *(float4*)(dist_out + (size_t)k0 * N_PTS + n0 + nl) = v0;
            *(float4*)(dist_out + (size_t)(k0 + 1) * N_PTS + n0 + nl) = v1;
            #pragma unroll
            for (int j = 0; j < 4; j++) {
                float va = dv[j].x, vb = dv[j].y;
                float mx = fmaxf(va, bd[j]);
                bk[j] = (va < bd[j]) ? k0 : bk[j];
                bd[j] = fminf(va, bd[j]);
                bs[j] = fminf(bs[j], mx);
                mx = fmaxf(vb, bd[j]);
                bk[j] = (vb < bd[j]) ? (k0 + 1) : bk[j];
                bd[j] = fminf(vb, bd[j]);
                bs[j] = fminf(bs[j], mx);
            }
        }
    }

    // ---- argmin reduce: shfl over lm (xor 8,16), then smem 2-round atomicMin --
    ull eH[4]; float d2H[4];
    #pragma unroll
    for (int j = 0; j < 4; j++) {
        ull e = ((ull)__float_as_uint(bd[j]) << 32) | (unsigned)bk[j];
        float d2 = bs[j];
        #pragma unroll
        for (int off = 8; off <= 16; off <<= 1) {
            ull oe = __shfl_xor_sync(0xffffffffu, e, off);
            float od2 = __shfl_xor_sync(0xffffffffu, d2, off);
            float od1 = __uint_as_float((unsigned)(oe >> 32));
            float md1 = __uint_as_float((unsigned)(e >> 32));
            if (oe < e) { d2 = fminf(od2, md1); e = oe; }
            else        { d2 = fminf(d2, od1); }
        }
        eH[j] = e; d2H[j] = d2;
        if (lm == 0) atomicMin(&s_e[nl + j], e);
    }
    __syncthreads();
    #pragma unroll
    for (int j = 0; j < 4; j++) {
        if (lm == 0) {
            ull cand = (eH[j] == s_e[nl + j])
                     ? ((((ull)__float_as_uint(d2H[j])) << 32) | 0xffffffffull)
                     : eH[j];
            atomicMin(&s_e2[nl + j], cand);
        }
    }
    __syncthreads();
    if (tid < 128) {
        ull be = s_e[tid];
        float d1f = __uint_as_float((unsigned)(be >> 32));
        float d2f = __uint_as_float((unsigned)(s_e2[tid] >> 32));
        int n = n0 + tid;
        assign_out[n] = (float)(unsigned)(be & 0xffffffffu);
        if (d2f - d1f < MARGIN) {
            int slot = atomicAdd(&g_nflag, 1);
            g_flag[slot] = n;
        }
    }
}

// ---------------- exact fp64 refinement for near-tied points ----------------
__global__ void __launch_bounds__(256, 2)
refine_kernel(const float* __restrict__ inp, const float* __restrict__ cen,
              float* __restrict__ assign_out)
{
    __shared__ float sx[8][D_DIM];
    const int wid = threadIdx.x >> 5, l = threadIdx.x & 31;
    const int gw = blockIdx.x * 8 + wid;
    const int nW = gridDim.x * 8;
    const int nf = g_nflag;
    for (int it = gw; it < nf; it += nW) {
        const int n = g_flag[it];
        for (int d = l; d < D_DIM; d += 32)
            sx[wid][d] = inp[(size_t)n * D_DIM + d];
        __syncwarp();
        double bestd = 1e300;
        int bestk = 0;
        for (int j = 0; j < 16; j++) {
            const int k = j * 32 + l;
            const float* c = cen + (size_t)k * D_DIM;
            double acc = 0.0;
            #pragma unroll 8
            for (int d = 0; d < D_DIM; d++) {
                double diff = (double)sx[wid][d] - (double)c[d];
                acc = fma(diff, diff, acc);
            }
            if (acc < bestd) { bestd = acc; bestk = k; }
        }
        #pragma unroll
        for (int off = 16; off; off >>= 1) {
            double od = __shfl_xor_sync(0xffffffffu, bestd, off);
            int ok = __shfl_xor_sync(0xffffffffu, bestk, off);
            if (od < bestd || (od == bestd && ok < bestk)) { bestd = od; bestk = ok; }
        }
        if (l == 0) assign_out[n] = (float)bestk;
        __syncwarp();
    }
}

// ---------------- launch ----------------
extern "C" void kernel_launch(void* const* d_in, const int* in_sizes, int n_in,
                              void* d_out, int out_size) {
    const float* inp = (const float*)d_in[0];
    const float* cen = (const float*)d_in[1];
    float* dist = (float*)d_out;
    long long need = (long long)K_CEN * N_PTS + N_PTS;
    float* assign = ((long long)out_size >= need) ? dist + (size_t)K_CEN * N_PTS
                                                  : dist;  // fallback, unused

    cudaFuncSetAttribute(kmeans_main, cudaFuncAttributeMaxDynamicSharedMemorySize,
                         SMEM_BYTES);

    transpose_c<<<dim3(K_CEN / 32, D_DIM / 32), 256>>>(cen);
    sq_kernel<<<N_PTS / 8, 256>>>(inp, N_PTS, 0);   // ||x||^2
    sq_kernel<<<K_CEN / 8, 256>>>(cen, K_CEN, 1);   // ||c||^2 + zero flag counter
    kmeans_main<<<N_PTS / 128, 256, SMEM_BYTES>>>(inp, dist, assign);
    refine_kernel<<<296, 256>>>(inp, cen, assign);
}